// round 8
// baseline (speedup 1.0000x reference)
#include <cuda_runtime.h>
#include <math.h>

#define RES_UP 0.05f
#define RES_DN 0.02f
#define REQ_UP 0.02f
#define REQ_DN 0.02f

#define MAXG 64

// ---------- packed f32x2 helpers: floats in/out, pack inside asm ----------
// r = a*b + c   (elementwise on the pair)
__device__ __forceinline__ void F2FMA(float& r0, float& r1,
    float a0, float a1, float b0, float b1, float c0, float c1) {
    asm("{\n\t.reg .b64 ra, rb, rc;\n\t"
        "mov.b64 ra, {%2,%3};\n\tmov.b64 rb, {%4,%5};\n\tmov.b64 rc, {%6,%7};\n\t"
        "fma.rn.f32x2 rc, ra, rb, rc;\n\tmov.b64 {%0,%1}, rc;\n\t}"
        : "=f"(r0), "=f"(r1)
        : "f"(a0), "f"(a1), "f"(b0), "f"(b1), "f"(c0), "f"(c1));
}
// r = a + b
__device__ __forceinline__ void F2ADD(float& r0, float& r1,
    float a0, float a1, float b0, float b1) {
    asm("{\n\t.reg .b64 ra, rb;\n\t"
        "mov.b64 ra, {%2,%3};\n\tmov.b64 rb, {%4,%5};\n\t"
        "add.rn.f32x2 ra, ra, rb;\n\tmov.b64 {%0,%1}, ra;\n\t}"
        : "=f"(r0), "=f"(r1)
        : "f"(a0), "f"(a1), "f"(b0), "f"(b1));
}
// r = a - b  (exact: fma(b,-1,a))
#define F2SUB(r0, r1, a0, a1, b0, b1) F2FMA(r0, r1, b0, b1, -1.f, -1.f, a0, a1)

// Fused: one block per batch element; one WARP per LP (timestep).
// Each lane owns gens (lane) [lo] and (lane+32) [hi] as one packed pair.
// Dead gens (g>=G) use poisoned constants (b=1e30, pmax=pmin=0) which pin
// their state at exactly 0 with no per-iteration masking.
// Objective reduced block-wide via smem in the epilogue.
__global__ __launch_bounds__(1024) void pdhg_fused_kernel(
    const float* __restrict__ forecast, const float* __restrict__ pminv,
    const float* __restrict__ pmaxv, const float* __restrict__ bv,
    const float* __restrict__ cv, const int* __restrict__ nitp,
    float* __restrict__ out, int G, int B, int T, float tau)
{
    __shared__ float sobj[32];
    const int bb   = blockIdx.x;
    const int w    = threadIdx.x >> 5;   // timestep
    const int lane = threadIdx.x & 31;
    const int t    = w;                  // blockDim = T*32, so t < T always
    const float D  = forecast[bb * T + t];
    const int nit  = *nitp;
    const float sig = tau;
    const float ntau = -tau, nsig = -sig;
    const float ruD = REQ_UP * D, rdD = REQ_DN * D;

    const int glo = lane, ghi = lane + 32;
    const float blo  = (glo < G) ? bv[glo]    : 1e30f;
    const float bhi  = (ghi < G) ? bv[ghi]    : 1e30f;
    const float pxlo = (glo < G) ? pmaxv[glo] : 0.f;
    const float pxhi = (ghi < G) ? pmaxv[ghi] : 0.f;
    const float pnlo = (glo < G) ? pminv[glo] : 0.f;
    const float pnhi = (ghi < G) ? pminv[ghi] : 0.f;
    const float tb0  = tau * blo,          tb1  = tau * bhi;
    const float tcu0 = tau * RES_UP * blo, tcu1 = tau * RES_UP * bhi;
    const float tcd0 = tau * RES_DN * blo, tcd1 = tau * RES_DN * bhi;
    const float spx0 = sig * pxlo,         spx1 = sig * pxhi;
    const float spn0 = sig * pnlo,         spn1 = sig * pnhi;

    // state: one packed pair per variable
    float P0 = 0, P1 = 0, Ru0 = 0, Ru1 = 0, Rd0 = 0, Rd1 = 0;
    float a0 = 0, a1 = 0, d0 = 0, d1 = 0, u0 = 0, u1 = 0, l0 = 0, l1 = 0;
    float y0 = 0.f, yu = 0.f, yd = 0.f;

#pragma unroll 2
    for (int it = 0; it < nit; ++it) {
        const float nty0 = ntau * y0;
        const float tyu  = tau * yu;
        const float tyd  = tau * yd;

        float t30, t31, s0, s1, e0, e1;
        // t3 = a - d + u - l
        F2SUB(t30, t31, a0, a1, d0, d1);
        F2SUB(s0, s1, u0, u1, l0, l1);
        F2ADD(t30, t31, t30, t31, s0, s1);
        // P_new = relu(P - tau*b - tau*y0 - tau*t3)
        F2SUB(e0, e1, P0, P1, tb0, tb1);
        F2ADD(e0, e1, e0, e1, nty0, nty0);
        F2FMA(e0, e1, t30, t31, ntau, ntau, e0, e1);
        float Pn0 = fmaxf(e0, 0.f), Pn1 = fmaxf(e1, 0.f);
        // Ru_new = relu(Ru - tau*cu - tau*a + tau*yu)
        F2SUB(e0, e1, Ru0, Ru1, tcu0, tcu1);
        F2ADD(e0, e1, e0, e1, tyu, tyu);
        F2FMA(e0, e1, a0, a1, ntau, ntau, e0, e1);
        float Run0 = fmaxf(e0, 0.f), Run1 = fmaxf(e1, 0.f);
        // Rd_new = relu(Rd - tau*cd - tau*d + tau*yd)
        F2SUB(e0, e1, Rd0, Rd1, tcd0, tcd1);
        F2ADD(e0, e1, e0, e1, tyd, tyd);
        F2FMA(e0, e1, d0, d1, ntau, ntau, e0, e1);
        float Rdn0 = fmaxf(e0, 0.f), Rdn1 = fmaxf(e1, 0.f);
        // x_bar = 2*x_new - x_old
        float Pb0, Pb1, Rub0, Rub1, Rdb0, Rdb1;
        F2ADD(e0, e1, Pn0, Pn1, Pn0, Pn1);
        F2SUB(Pb0, Pb1, e0, e1, P0, P1);
        F2ADD(e0, e1, Run0, Run1, Run0, Run1);
        F2SUB(Rub0, Rub1, e0, e1, Ru0, Ru1);
        F2ADD(e0, e1, Rdn0, Rdn1, Rdn0, Rdn1);
        F2SUB(Rdb0, Rdb1, e0, e1, Rd0, Rd1);
        P0 = Pn0; P1 = Pn1; Ru0 = Run0; Ru1 = Run1; Rd0 = Rdn0; Rd1 = Rdn1;

        // lane-local partials (pair collapse)
        float sP  = Pb0 + Pb1;
        float sRu = Rub0 + Rub1;
        float sRd = Rdb0 + Rdb1;

        // 5-stage full-warp butterfly; dual updates interleaved to fill
        // SHFL latency (they depend only on lane-local x_bar).
        sP  += __shfl_xor_sync(0xffffffffu, sP,  16);
        sRu += __shfl_xor_sync(0xffffffffu, sRu, 16);
        sRd += __shfl_xor_sync(0xffffffffu, sRd, 16);
        {   // a-update
            float q0, q1;
            F2ADD(q0, q1, Pb0, Pb1, Rub0, Rub1);
            F2SUB(e0, e1, a0, a1, spx0, spx1);
            F2FMA(e0, e1, q0, q1, sig, sig, e0, e1);
            a0 = fmaxf(e0, 0.f); a1 = fmaxf(e1, 0.f);
        }
        sP  += __shfl_xor_sync(0xffffffffu, sP,  8);
        sRu += __shfl_xor_sync(0xffffffffu, sRu, 8);
        sRd += __shfl_xor_sync(0xffffffffu, sRd, 8);
        {   // d-update
            float q0, q1;
            F2SUB(q0, q1, Rdb0, Rdb1, Pb0, Pb1);
            F2ADD(e0, e1, d0, d1, spn0, spn1);
            F2FMA(e0, e1, q0, q1, sig, sig, e0, e1);
            d0 = fmaxf(e0, 0.f); d1 = fmaxf(e1, 0.f);
        }
        sP  += __shfl_xor_sync(0xffffffffu, sP,  4);
        sRu += __shfl_xor_sync(0xffffffffu, sRu, 4);
        sRd += __shfl_xor_sync(0xffffffffu, sRd, 4);
        {   // u-update
            F2SUB(e0, e1, u0, u1, spx0, spx1);
            F2FMA(e0, e1, Pb0, Pb1, sig, sig, e0, e1);
            u0 = fmaxf(e0, 0.f); u1 = fmaxf(e1, 0.f);
        }
        sP  += __shfl_xor_sync(0xffffffffu, sP,  2);
        sRu += __shfl_xor_sync(0xffffffffu, sRu, 2);
        sRd += __shfl_xor_sync(0xffffffffu, sRd, 2);
        {   // l-update
            F2ADD(e0, e1, l0, l1, spn0, spn1);
            F2FMA(e0, e1, Pb0, Pb1, nsig, nsig, e0, e1);
            l0 = fmaxf(e0, 0.f); l1 = fmaxf(e1, 0.f);
        }
        sP  += __shfl_xor_sync(0xffffffffu, sP,  1);
        sRu += __shfl_xor_sync(0xffffffffu, sRu, 1);
        sRd += __shfl_xor_sync(0xffffffffu, sRd, 1);

        // scalar dual rows
        y0 = fmaf(sig, sP - D, y0);
        yu = fmaxf(fmaf(nsig, sRu, fmaf(sig, ruD, yu)), 0.f);
        yd = fmaxf(fmaf(nsig, sRd, fmaf(sig, rdD, yd)), 0.f);
    }

    // outputs: P_DA | R_up | R_dn | obj | Cost_DA, all (B, G, T)
    size_t BGT = (size_t)B * G * T;
    float* Pout = out;
    float* Ruo  = out + BGT;
    float* Rdo  = out + 2 * BGT;
    float* Co   = out + 3 * BGT + B;

    float part = 0.f;
    if (glo < G) {
        size_t i = ((size_t)bb * G + glo) * T + t;
        float co = fmaf(blo, P0, cv[glo]);
        Pout[i] = P0; Ruo[i] = Ru0; Rdo[i] = Rd0; Co[i] = co;
        part += co + RES_UP * blo * Ru0 + RES_DN * blo * Rd0;
    }
    if (ghi < G) {
        size_t i = ((size_t)bb * G + ghi) * T + t;
        float co = fmaf(bhi, P1, cv[ghi]);
        Pout[i] = P1; Ruo[i] = Ru1; Rdo[i] = Rd1; Co[i] = co;
        part += co + RES_UP * bhi * Ru1 + RES_DN * bhi * Rd1;
    }
#pragma unroll
    for (int k = 16; k > 0; k >>= 1)
        part += __shfl_xor_sync(0xffffffffu, part, k);
    if (lane == 0) sobj[w] = part;
    __syncthreads();

    // block reduction of T per-LP partials -> obj[bb] (warp 0)
    if (w == 0) {
        float v = (lane < T) ? sobj[lane] : 0.f;
#pragma unroll
        for (int k = 16; k > 0; k >>= 1)
            v += __shfl_xor_sync(0xffffffffu, v, k);
        if (lane == 0) out[3 * BGT + bb] = v;
    }
}

// ---------------- host: structured spectral norm of K (power iteration) -----
static void K_matvec(const double* v, double* w, int G) {
    int n1 = G, n2 = 2 * G;
    double s0 = 0, s1 = 0, s2 = 0;
    for (int g = 0; g < G; ++g) { s0 += v[g]; s1 += v[n1 + g]; s2 += v[n2 + g]; }
    w[0] = s0;
    for (int g = 0; g < G; ++g) {
        w[1 + g]          =  v[g] + v[n1 + g];
        w[1 + G + g]      = -v[g] + v[n2 + g];
        w[1 + 2 * G + g]  =  v[g];
        w[1 + 3 * G + g]  = -v[g];
    }
    w[1 + 4 * G]     = -s1;
    w[1 + 4 * G + 1] = -s2;
}

static void KT_matvec(const double* w, double* z, int G) {
    double yu = w[1 + 4 * G], yd = w[1 + 4 * G + 1];
    for (int g = 0; g < G; ++g) {
        z[g]           = w[0] + w[1 + g] - w[1 + G + g] + w[1 + 2 * G + g] - w[1 + 3 * G + g];
        z[G + g]       = w[1 + g] - yu;
        z[2 * G + g]   = w[1 + G + g] - yd;
    }
}

static double spectral_norm_K(int G) {
    static double v[3 * MAXG], w[4 * MAXG + 3], z[3 * MAXG];
    int n = 3 * G;
    for (int i = 0; i < n; ++i) v[i] = 1.0 + 0.001 * (double)(i % 7);
    double lam = 1.0;
    for (int it = 0; it < 4000; ++it) {
        K_matvec(v, w, G);
        KT_matvec(w, z, G);
        double nrm = 0.0;
        for (int i = 0; i < n; ++i) nrm += z[i] * z[i];
        nrm = sqrt(nrm);
        lam = nrm;
        double inv = 1.0 / nrm;
        for (int i = 0; i < n; ++i) v[i] = z[i] * inv;
    }
    return sqrt(lam);  // sigma_max(K)
}

extern "C" void kernel_launch(void* const* d_in, const int* in_sizes, int n_in,
                              void* d_out, int out_size) {
    const float* forecast = (const float*)d_in[0];
    const float* pminv    = (const float*)d_in[1];
    const float* pmaxv    = (const float*)d_in[2];
    const float* bv       = (const float*)d_in[3];
    const float* cv       = (const float*)d_in[4];
    const int*   nitp     = (const int*)d_in[5];

    int G  = in_sizes[1];
    int BT = in_sizes[0];
    // out_size = 4*B*G*T + B  with  B*T = BT  ->  B = out_size - 4*G*BT
    int B = out_size - 4 * G * BT;
    if (B <= 0) B = 1;
    int T = BT / B;
    if (T > 32) T = 32;  // shape guard (problem uses T=24)

    double L = spectral_norm_K(G);
    float tau = (float)(0.9 / L);

    float* out = (float*)d_out;
    pdhg_fused_kernel<<<B, T * 32>>>(
        forecast, pminv, pmaxv, bv, cv, nitp, out, G, B, T, tau);
}

// round 9
// speedup vs baseline: 1.1406x; 1.1406x over previous
#include <cuda_runtime.h>
#include <math.h>

#define RES_UP 0.05f
#define RES_DN 0.02f
#define REQ_UP 0.02f
#define REQ_DN 0.02f

#define MAXG 64

// per-LP objective partials + per-batch completion counters
__device__ float g_partial[8192];
__device__ int   g_count[1024];   // zero-init; reset by last block (replay-safe)

// ---------- packed f32x2 helpers: floats in/out, pack inside asm ----------
__device__ __forceinline__ void F2FMA(float& r0, float& r1,
    float a0, float a1, float b0, float b1, float c0, float c1) {
    asm("{\n\t.reg .b64 ra, rb, rc;\n\t"
        "mov.b64 ra, {%2,%3};\n\tmov.b64 rb, {%4,%5};\n\tmov.b64 rc, {%6,%7};\n\t"
        "fma.rn.f32x2 rc, ra, rb, rc;\n\tmov.b64 {%0,%1}, rc;\n\t}"
        : "=f"(r0), "=f"(r1)
        : "f"(a0), "f"(a1), "f"(b0), "f"(b1), "f"(c0), "f"(c1));
}
__device__ __forceinline__ void F2ADD(float& r0, float& r1,
    float a0, float a1, float b0, float b1) {
    asm("{\n\t.reg .b64 ra, rb;\n\t"
        "mov.b64 ra, {%2,%3};\n\tmov.b64 rb, {%4,%5};\n\t"
        "add.rn.f32x2 ra, ra, rb;\n\tmov.b64 {%0,%1}, ra;\n\t}"
        : "=f"(r0), "=f"(r1)
        : "f"(a0), "f"(a1), "f"(b0), "f"(b1));
}
#define F2SUB(r0, r1, a0, a1, b0, b1) F2FMA(r0, r1, b0, b1, -1.f, -1.f, a0, a1)

// One-warp blocks; each 16-lane group owns one LP (batch bb, timestep t).
// 4 gen slots/lane (g = 16*s + gl). Dead gens (g>=G) use poisoned constants
// (b=1e30, pmax=pmin=0) which pin their state at exactly 0.
// Last block per batch (threadfence+counter) reduces the T partials -> obj.
__global__ __launch_bounds__(32) void pdhg_kernel(
    const float* __restrict__ forecast, const float* __restrict__ pminv,
    const float* __restrict__ pmaxv, const float* __restrict__ bv,
    const float* __restrict__ cv, const int* __restrict__ nitp,
    float* __restrict__ out, int G, int B, int T, int bpb, float tau)
{
    const int lane = threadIdx.x;
    const int grp  = lane >> 4;
    const int gl   = lane & 15;
    const int bb   = blockIdx.x / bpb;
    const int t    = 2 * (blockIdx.x - bb * bpb) + grp;
    const bool live = t < T;
    const int tc   = live ? t : T - 1;
    const float D  = forecast[bb * T + tc];
    const int nit  = *nitp;
    const float sig = tau;
    const float ntau = -tau, nsig = -sig;
    const float ruD = REQ_UP * D, rdD = REQ_DN * D;

    float tb[4], tcu[4], tcd[4], spx[4], spn[4];
#pragma unroll
    for (int s = 0; s < 4; ++s) {
        int g = 16 * s + gl;
        float bg = (g < G) ? bv[g]    : 1e30f;
        float px = (g < G) ? pmaxv[g] : 0.f;
        float pn = (g < G) ? pminv[g] : 0.f;
        tb[s]  = tau * bg;
        tcu[s] = tau * RES_UP * bg;
        tcd[s] = tau * RES_DN * bg;
        spx[s] = sig * px;
        spn[s] = sig * pn;
    }

    float P[4]  = {0,0,0,0}, Ru[4] = {0,0,0,0}, Rd[4] = {0,0,0,0};
    float av[4] = {0,0,0,0}, dv[4] = {0,0,0,0}, uv[4] = {0,0,0,0}, lv[4] = {0,0,0,0};
    float y0 = 0.f, yu = 0.f, yd = 0.f;

    for (int it = 0; it < nit; ++it) {
        const float nty0 = ntau * y0;
        const float tyu  = tau * yu;
        const float tyd  = tau * yd;

        float Pb[4], Rub[4], Rdb[4];
#pragma unroll
        for (int q = 0; q < 2; ++q) {
            const int i = 2 * q, j = i + 1;
            float t0, t1, s0, s1, e0, e1;
            F2SUB(t0, t1, av[i], av[j], dv[i], dv[j]);
            F2SUB(s0, s1, uv[i], uv[j], lv[i], lv[j]);
            F2ADD(t0, t1, t0, t1, s0, s1);
            F2SUB(e0, e1, P[i], P[j], tb[i], tb[j]);
            F2ADD(e0, e1, e0, e1, nty0, nty0);
            F2FMA(e0, e1, t0, t1, ntau, ntau, e0, e1);
            float Pn0 = fmaxf(e0, 0.f), Pn1 = fmaxf(e1, 0.f);
            F2SUB(e0, e1, Ru[i], Ru[j], tcu[i], tcu[j]);
            F2ADD(e0, e1, e0, e1, tyu, tyu);
            F2FMA(e0, e1, av[i], av[j], ntau, ntau, e0, e1);
            float Run0 = fmaxf(e0, 0.f), Run1 = fmaxf(e1, 0.f);
            F2SUB(e0, e1, Rd[i], Rd[j], tcd[i], tcd[j]);
            F2ADD(e0, e1, e0, e1, tyd, tyd);
            F2FMA(e0, e1, dv[i], dv[j], ntau, ntau, e0, e1);
            float Rdn0 = fmaxf(e0, 0.f), Rdn1 = fmaxf(e1, 0.f);
            F2ADD(e0, e1, Pn0, Pn1, Pn0, Pn1);
            F2SUB(Pb[i], Pb[j], e0, e1, P[i], P[j]);
            F2ADD(e0, e1, Run0, Run1, Run0, Run1);
            F2SUB(Rub[i], Rub[j], e0, e1, Ru[i], Ru[j]);
            F2ADD(e0, e1, Rdn0, Rdn1, Rdn0, Rdn1);
            F2SUB(Rdb[i], Rdb[j], e0, e1, Rd[i], Rd[j]);
            P[i] = Pn0; P[j] = Pn1; Ru[i] = Run0; Ru[j] = Run1; Rd[i] = Rdn0; Rd[j] = Rdn1;
        }

        float sP, sRu, sRd, h0, h1;
        F2ADD(h0, h1, Pb[0], Pb[1], Pb[2], Pb[3]);     sP  = h0 + h1;
        F2ADD(h0, h1, Rub[0], Rub[1], Rub[2], Rub[3]); sRu = h0 + h1;
        F2ADD(h0, h1, Rdb[0], Rdb[1], Rdb[2], Rdb[3]); sRd = h0 + h1;

        sP  += __shfl_xor_sync(0xffffffffu, sP,  8);
        sRu += __shfl_xor_sync(0xffffffffu, sRu, 8);
        sRd += __shfl_xor_sync(0xffffffffu, sRd, 8);
        {   // pair 0: a, d
            float t0, t1, e0, e1;
            F2ADD(t0, t1, Pb[0], Pb[1], Rub[0], Rub[1]);
            F2SUB(e0, e1, av[0], av[1], spx[0], spx[1]);
            F2FMA(e0, e1, t0, t1, sig, sig, e0, e1);
            av[0] = fmaxf(e0, 0.f); av[1] = fmaxf(e1, 0.f);
            F2SUB(t0, t1, Rdb[0], Rdb[1], Pb[0], Pb[1]);
            F2ADD(e0, e1, dv[0], dv[1], spn[0], spn[1]);
            F2FMA(e0, e1, t0, t1, sig, sig, e0, e1);
            dv[0] = fmaxf(e0, 0.f); dv[1] = fmaxf(e1, 0.f);
        }
        sP  += __shfl_xor_sync(0xffffffffu, sP,  4);
        sRu += __shfl_xor_sync(0xffffffffu, sRu, 4);
        sRd += __shfl_xor_sync(0xffffffffu, sRd, 4);
        {   // pair 0: u, l
            float e0, e1;
            F2SUB(e0, e1, uv[0], uv[1], spx[0], spx[1]);
            F2FMA(e0, e1, Pb[0], Pb[1], sig, sig, e0, e1);
            uv[0] = fmaxf(e0, 0.f); uv[1] = fmaxf(e1, 0.f);
            F2ADD(e0, e1, lv[0], lv[1], spn[0], spn[1]);
            F2FMA(e0, e1, Pb[0], Pb[1], nsig, nsig, e0, e1);
            lv[0] = fmaxf(e0, 0.f); lv[1] = fmaxf(e1, 0.f);
        }
        sP  += __shfl_xor_sync(0xffffffffu, sP,  2);
        sRu += __shfl_xor_sync(0xffffffffu, sRu, 2);
        sRd += __shfl_xor_sync(0xffffffffu, sRd, 2);
        {   // pair 1: a, d
            float t0, t1, e0, e1;
            F2ADD(t0, t1, Pb[2], Pb[3], Rub[2], Rub[3]);
            F2SUB(e0, e1, av[2], av[3], spx[2], spx[3]);
            F2FMA(e0, e1, t0, t1, sig, sig, e0, e1);
            av[2] = fmaxf(e0, 0.f); av[3] = fmaxf(e1, 0.f);
            F2SUB(t0, t1, Rdb[2], Rdb[3], Pb[2], Pb[3]);
            F2ADD(e0, e1, dv[2], dv[3], spn[2], spn[3]);
            F2FMA(e0, e1, t0, t1, sig, sig, e0, e1);
            dv[2] = fmaxf(e0, 0.f); dv[3] = fmaxf(e1, 0.f);
        }
        sP  += __shfl_xor_sync(0xffffffffu, sP,  1);
        sRu += __shfl_xor_sync(0xffffffffu, sRu, 1);
        sRd += __shfl_xor_sync(0xffffffffu, sRd, 1);
        {   // pair 1: u, l
            float e0, e1;
            F2SUB(e0, e1, uv[2], uv[3], spx[2], spx[3]);
            F2FMA(e0, e1, Pb[2], Pb[3], sig, sig, e0, e1);
            uv[2] = fmaxf(e0, 0.f); uv[3] = fmaxf(e1, 0.f);
            F2ADD(e0, e1, lv[2], lv[3], spn[2], spn[3]);
            F2FMA(e0, e1, Pb[2], Pb[3], nsig, nsig, e0, e1);
            lv[2] = fmaxf(e0, 0.f); lv[3] = fmaxf(e1, 0.f);
        }

        y0 = fmaf(sig, sP - D, y0);
        yu = fmaxf(fmaf(nsig, sRu, fmaf(sig, ruD, yu)), 0.f);
        yd = fmaxf(fmaf(nsig, sRd, fmaf(sig, rdD, yd)), 0.f);
    }

    // outputs: P_DA | R_up | R_dn | obj | Cost_DA, all (B, G, T)
    size_t BGT = (size_t)B * G * T;
    float* Pout = out;
    float* Ruo  = out + BGT;
    float* Rdo  = out + 2 * BGT;
    float* Co   = out + 3 * BGT + B;

    float part = 0.f;
    if (live) {
#pragma unroll
        for (int s = 0; s < 4; ++s) {
            int g = 16 * s + gl;
            if (g < G) {
                size_t i = ((size_t)bb * G + g) * T + t;
                float bg = bv[g];
                float co = fmaf(bg, P[s], cv[g]);
                Pout[i] = P[s]; Ruo[i] = Ru[s]; Rdo[i] = Rd[s]; Co[i] = co;
                part += co + RES_UP * bg * Ru[s] + RES_DN * bg * Rd[s];
            }
        }
    }
#pragma unroll
    for (int k = 8; k > 0; k >>= 1)
        part += __shfl_xor_sync(0xffffffffu, part, k);
    if (live && gl == 0) g_partial[bb * T + t] = part;

    // last block of this batch reduces the T partials (fixed order, determ.)
    __syncwarp();
    int done = 0;
    if (lane == 0) {
        __threadfence();
        int old = atomicAdd(&g_count[bb], 1);
        done = (old == bpb - 1);
    }
    done = __shfl_sync(0xffffffffu, done, 0);
    if (done) {
        __threadfence();
        float v = (lane < T) ? g_partial[bb * T + lane] : 0.f;
        if (32 + lane < T) v += g_partial[bb * T + 32 + lane];
#pragma unroll
        for (int k = 16; k > 0; k >>= 1)
            v += __shfl_xor_sync(0xffffffffu, v, k);
        if (lane == 0) {
            out[3 * BGT + bb] = v;
            g_count[bb] = 0;   // reset for next graph replay
        }
    }
}

// ---------------- host: structured spectral norm of K (power iteration) -----
static void K_matvec(const double* v, double* w, int G) {
    int n1 = G, n2 = 2 * G;
    double s0 = 0, s1 = 0, s2 = 0;
    for (int g = 0; g < G; ++g) { s0 += v[g]; s1 += v[n1 + g]; s2 += v[n2 + g]; }
    w[0] = s0;
    for (int g = 0; g < G; ++g) {
        w[1 + g]          =  v[g] + v[n1 + g];
        w[1 + G + g]      = -v[g] + v[n2 + g];
        w[1 + 2 * G + g]  =  v[g];
        w[1 + 3 * G + g]  = -v[g];
    }
    w[1 + 4 * G]     = -s1;
    w[1 + 4 * G + 1] = -s2;
}

static void KT_matvec(const double* w, double* z, int G) {
    double yu = w[1 + 4 * G], yd = w[1 + 4 * G + 1];
    for (int g = 0; g < G; ++g) {
        z[g]           = w[0] + w[1 + g] - w[1 + G + g] + w[1 + 2 * G + g] - w[1 + 3 * G + g];
        z[G + g]       = w[1 + g] - yu;
        z[2 * G + g]   = w[1 + G + g] - yd;
    }
}

static double spectral_norm_K(int G) {
    static double v[3 * MAXG], w[4 * MAXG + 3], z[3 * MAXG];
    int n = 3 * G;
    for (int i = 0; i < n; ++i) v[i] = 1.0 + 0.001 * (double)(i % 7);
    double lam = 1.0;
    for (int it = 0; it < 4000; ++it) {
        K_matvec(v, w, G);
        KT_matvec(w, z, G);
        double nrm = 0.0;
        for (int i = 0; i < n; ++i) nrm += z[i] * z[i];
        nrm = sqrt(nrm);
        lam = nrm;
        double inv = 1.0 / nrm;
        for (int i = 0; i < n; ++i) v[i] = z[i] * inv;
    }
    return sqrt(lam);  // sigma_max(K)
}

extern "C" void kernel_launch(void* const* d_in, const int* in_sizes, int n_in,
                              void* d_out, int out_size) {
    const float* forecast = (const float*)d_in[0];
    const float* pminv    = (const float*)d_in[1];
    const float* pmaxv    = (const float*)d_in[2];
    const float* bv       = (const float*)d_in[3];
    const float* cv       = (const float*)d_in[4];
    const int*   nitp     = (const int*)d_in[5];

    int G  = in_sizes[1];
    int BT = in_sizes[0];
    // out_size = 4*B*G*T + B  with  B*T = BT  ->  B = out_size - 4*G*BT
    int B = out_size - 4 * G * BT;
    if (B <= 0) B = 1;
    int T = BT / B;

    double L = spectral_norm_K(G);
    float tau = (float)(0.9 / L);

    float* out = (float*)d_out;
    int bpb = (T + 1) / 2;     // one-warp blocks per batch element
    pdhg_kernel<<<B * bpb, 32>>>(
        forecast, pminv, pmaxv, bv, cv, nitp, out, G, B, T, bpb, tau);
}